// round 12
// baseline (speedup 1.0000x reference)
#include <cuda_runtime.h>
#include <cuda_fp16.h>
#include <cstdint>

#define NB   8
#define QDIM 2048
#define KDIM 2048
#define EDIM 512

typedef __half fp16;

// ---------------------------------------------------------------------------
// Device-global scratch (allocation-guard-safe)
// ---------------------------------------------------------------------------
__device__ __align__(256) fp16  g_Qh[(size_t)NB * QDIM * EDIM];
__device__ __align__(256) fp16  g_Ql[(size_t)NB * QDIM * EDIM];
__device__ __align__(256) fp16  g_Kh[(size_t)NB * KDIM * EDIM];
__device__ __align__(256) fp16  g_Kl[(size_t)NB * KDIM * EDIM];
__device__ __align__(256) fp16  g_Vth[(size_t)NB * EDIM * KDIM];  // V^T [b][e][k]
__device__ __align__(256) fp16  g_Vtl[(size_t)NB * EDIM * KDIM];
__device__ __align__(256) float g_E  [(size_t)NB * QDIM * KDIM];  // logits
__device__ __align__(256) fp16  g_Ph [(size_t)NB * QDIM * KDIM];  // softmax (hi only)

// ---------------------------------------------------------------------------
// PTX helpers (plain sm_80+ features only — virtual arch is compute_103)
// ---------------------------------------------------------------------------
__device__ __forceinline__ uint32_t smem_u32(const void* p) {
    uint32_t a;
    asm("{ .reg .u64 t; cvta.to.shared.u64 t, %1; cvt.u32.u64 %0, t; }" : "=r"(a) : "l"(p));
    return a;
}

__device__ __forceinline__ uint32_t h2_u32(__half2 h) {
    union { __half2 h; uint32_t u; } c;
    c.h = h;
    return c.u;
}

#define CP_ASYNC16(dst, src) \
    asm volatile("cp.async.cg.shared.global [%0], [%1], 16;" :: "r"(dst), "l"(src))
#define CP_COMMIT() asm volatile("cp.async.commit_group;" ::: "memory")
#define CP_WAIT1()  asm volatile("cp.async.wait_group 1;" ::: "memory")
#define CP_WAIT0()  asm volatile("cp.async.wait_group 0;" ::: "memory")

#define LDSM_X4(r0, r1, r2, r3, a)                                          \
    asm volatile("ldmatrix.sync.aligned.m8n8.x4.shared.b16 {%0,%1,%2,%3}, [%4];" \
        : "=r"(r0), "=r"(r1), "=r"(r2), "=r"(r3) : "r"(a))

#define MMA16816(d, a, b0, b1)                                              \
    asm volatile("mma.sync.aligned.m16n8k16.row.col.f32.f16.f16.f32 "       \
        "{%0,%1,%2,%3},{%4,%5,%6,%7},{%8,%9},{%0,%1,%2,%3};"                \
        : "+f"((d)[0]), "+f"((d)[1]), "+f"((d)[2]), "+f"((d)[3])            \
        : "r"((a)[0]), "r"((a)[1]), "r"((a)[2]), "r"((a)[3]),               \
          "r"(b0), "r"(b1))

// ---------------------------------------------------------------------------
// Elementwise fp32 -> fp16 hi/lo split, Q and K in one launch (blockIdx.y)
// ---------------------------------------------------------------------------
__global__ __launch_bounds__(256)
void split2_kernel(const float* __restrict__ Q, const float* __restrict__ K,
                   int n4)
{
    const int which = blockIdx.y;
    const float* X = which ? K : Q;
    fp16* Xh = which ? g_Kh : g_Qh;
    fp16* Xl = which ? g_Kl : g_Ql;
    int i = blockIdx.x * 256 + threadIdx.x;
    if (i >= n4) return;
    float4 v = ((const float4*)X)[i];
    fp16 h0 = __float2half_rn(v.x), h1 = __float2half_rn(v.y);
    fp16 h2 = __float2half_rn(v.z), h3 = __float2half_rn(v.w);
    fp16 l0 = __float2half_rn(v.x - __half2float(h0));
    fp16 l1 = __float2half_rn(v.y - __half2float(h1));
    fp16 l2 = __float2half_rn(v.z - __half2float(h2));
    fp16 l3 = __float2half_rn(v.w - __half2float(h3));
    ((__half2*)Xh)[2 * i]     = __half2(h0, h1);
    ((__half2*)Xh)[2 * i + 1] = __half2(h2, h3);
    ((__half2*)Xl)[2 * i]     = __half2(l0, l1);
    ((__half2*)Xl)[2 * i + 1] = __half2(l2, l3);
}

// ---------------------------------------------------------------------------
// V [b][k][e] fp32 -> V^T [b][e][k] fp16 hi/lo
// ---------------------------------------------------------------------------
__global__ __launch_bounds__(256)
void vtrans_kernel(const float* __restrict__ V)
{
    __shared__ float t[32][33];
    const int b  = blockIdx.z;
    const int k0 = blockIdx.x * 32;
    const int e0 = blockIdx.y * 32;
    const int tx = threadIdx.x & 31;
    const int ty = threadIdx.x >> 5;
    const float* Vb = V + (size_t)b * KDIM * EDIM;

    #pragma unroll
    for (int j = 0; j < 4; j++)
        t[ty + j * 8][tx] = Vb[(size_t)(k0 + ty + j * 8) * EDIM + e0 + tx];
    __syncthreads();

    #pragma unroll
    for (int j = 0; j < 4; j++) {
        int e = e0 + ty + j * 8;
        int k = k0 + tx;
        float x = t[tx][ty + j * 8];
        fp16 h = __float2half_rn(x);
        fp16 l = __float2half_rn(x - __half2float(h));
        size_t o = (size_t)b * EDIM * KDIM + (size_t)e * KDIM + k;
        g_Vth[o] = h;
        g_Vtl[o] = l;
    }
}

// ---------------------------------------------------------------------------
// Row softmax of g_E -> fp16 (hi only) in g_Ph  (float4 I/O)
// ---------------------------------------------------------------------------
__global__ __launch_bounds__(256)
void softmax_split_kernel()
{
    const size_t row = blockIdx.x;
    const float* p = g_E + row * (size_t)KDIM;
    const int tid = threadIdx.x;

    float4 va = ((const float4*)p)[tid];
    float4 vb = ((const float4*)p)[tid + 256];

    float m = fmaxf(fmaxf(fmaxf(va.x, va.y), fmaxf(va.z, va.w)),
                    fmaxf(fmaxf(vb.x, vb.y), fmaxf(vb.z, vb.w)));

    __shared__ float red[8];
    #pragma unroll
    for (int off = 16; off > 0; off >>= 1) m = fmaxf(m, __shfl_xor_sync(~0u, m, off));
    if ((tid & 31) == 0) red[tid >> 5] = m;
    __syncthreads();
    if (tid < 8) {
        float t = red[tid];
        #pragma unroll
        for (int off = 4; off > 0; off >>= 1) t = fmaxf(t, __shfl_xor_sync(0xFFu, t, off));
        red[tid] = t;
    }
    __syncthreads();
    m = red[0];

    va.x = __expf(va.x - m); va.y = __expf(va.y - m);
    va.z = __expf(va.z - m); va.w = __expf(va.w - m);
    vb.x = __expf(vb.x - m); vb.y = __expf(vb.y - m);
    vb.z = __expf(vb.z - m); vb.w = __expf(vb.w - m);
    float s = (va.x + va.y) + (va.z + va.w) + (vb.x + vb.y) + (vb.z + vb.w);

    __shared__ float red2[8];
    #pragma unroll
    for (int off = 16; off > 0; off >>= 1) s += __shfl_xor_sync(~0u, s, off);
    if ((tid & 31) == 0) red2[tid >> 5] = s;
    __syncthreads();
    if (tid < 8) {
        float t = red2[tid];
        #pragma unroll
        for (int off = 4; off > 0; off >>= 1) t += __shfl_xor_sync(0xFFu, t, off);
        red2[tid] = t;
    }
    __syncthreads();
    const float inv = 1.0f / red2[0];

    fp16* ph = g_Ph + row * (size_t)KDIM;
    __half2 hh[4];
    hh[0] = __half2(__float2half_rn(va.x * inv), __float2half_rn(va.y * inv));
    hh[1] = __half2(__float2half_rn(va.z * inv), __float2half_rn(va.w * inv));
    hh[2] = __half2(__float2half_rn(vb.x * inv), __float2half_rn(vb.y * inv));
    hh[3] = __half2(__float2half_rn(vb.z * inv), __float2half_rn(vb.w * inv));
    *(uint2*)&ph[tid * 4]        = make_uint2(h2_u32(hh[0]), h2_u32(hh[1]));
    *(uint2*)&ph[1024 + tid * 4] = make_uint2(h2_u32(hh[2]), h2_u32(hh[3]));
}

// ---------------------------------------------------------------------------
// HMMA split-fp16 GEMM: 2 CTAs/SM + pipelined ring + DRIP-FED fills.
//   MODE 0 (3 passes): E = Q.K^T. K-chunk 32, packed 128B rows [hi32|lo32],
//                      3 stages x 32KB. 8 fill parts over 6 MMA steps.
//   MODE 1 (2 passes): O = P.V.  K-chunk 64, tiles Ph/Vh/Vl, 2 stages x 48KB.
//                      12 fill parts front-loaded into first 4 of 8 MMA steps.
// The drip spreads LDGSTS issue (rt=8cyc/SMSP) across tensor-busy time
// instead of clustering it in a post-barrier fill phase.
// ---------------------------------------------------------------------------
#define TILE16K 16384u

__device__ __forceinline__ void cp_pack(uint32_t dstbase, const fp16* srcH,
                                        const fp16* srcL, int ld, int tid)
{
    const char* sh = (const char*)srcH;
    const char* sl = (const char*)srcL;
    const size_t row_bytes = (size_t)ld * 2;
    #pragma unroll
    for (int p = 0; p < 4; ++p) {
        int idx = tid + p * 256;
        int r = idx >> 3;
        int c = idx & 7;
        const char* src = (c < 4) ? sh + (size_t)r * row_bytes + c * 16
                                  : sl + (size_t)r * row_bytes + (c - 4) * 16;
        uint32_t dst = dstbase + (uint32_t)r * 128u + (uint32_t)((c ^ (r & 7)) << 4);
        CP_ASYNC16(dst, src);
    }
}

__device__ __forceinline__ void cp_tile(uint32_t dstbase, const fp16* src,
                                        int ld, int tid)
{
    const char* s = (const char*)src;
    const size_t row_bytes = (size_t)ld * 2;
    const int c = tid & 7;
    #pragma unroll
    for (int r0 = 0; r0 < 128; r0 += 32) {
        int r = r0 + (tid >> 3);
        uint32_t dst = dstbase + (uint32_t)r * 128u + (uint32_t)((c ^ (r & 7)) << 4);
        CP_ASYNC16(dst, s + (size_t)r * row_bytes + c * 16);
    }
}

__device__ __forceinline__ void lds_a(uint32_t base, int cbase, int wm,
                                      int a_r15, int c_hi, uint32_t af[4][4])
{
    #pragma unroll
    for (int mi = 0; mi < 4; ++mi) {
        const int row = wm + mi * 16 + a_r15;
        const uint32_t addr = base + (uint32_t)row * 128u
            + (uint32_t)(((cbase + c_hi) ^ (row & 7)) << 4);
        LDSM_X4(af[mi][0], af[mi][1], af[mi][2], af[mi][3], addr);
    }
}

__device__ __forceinline__ void lds_b(uint32_t base, int cbase, int wn,
                                      int a_r15, int c_hi, uint32_t bf[2][4])
{
    #pragma unroll
    for (int nj = 0; nj < 2; ++nj) {
        const int row = wn + nj * 16 + a_r15;
        const uint32_t addr = base + (uint32_t)row * 128u
            + (uint32_t)(((cbase + c_hi) ^ (row & 7)) << 4);
        LDSM_X4(bf[nj][0], bf[nj][1], bf[nj][2], bf[nj][3], addr);
    }
}

__device__ __forceinline__ void mma_step(float acc[4][4][4],
                                         uint32_t af[4][4], uint32_t bf[2][4])
{
    #pragma unroll
    for (int mi = 0; mi < 4; ++mi) {
        #pragma unroll
        for (int ni = 0; ni < 4; ++ni) {
            const uint32_t b0 = bf[ni >> 1][(ni & 1) ? 1 : 0];
            const uint32_t b1 = bf[ni >> 1][(ni & 1) ? 3 : 2];
            MMA16816(acc[mi][ni], af[mi], b0, b1);
        }
    }
}

template <int MODE>
__global__ __launch_bounds__(256, 2)
void hgemm3_kernel(float* __restrict__ Oout)
{
    constexpr int LDA  = (MODE == 0) ? EDIM : KDIM;
    constexpr int LDB  = (MODE == 0) ? EDIM : KDIM;
    constexpr int LDC  = (MODE == 0) ? KDIM : EDIM;
    constexpr int KTOT = (MODE == 0) ? EDIM : KDIM;
    constexpr int KCH  = (MODE == 0) ? 32 : 64;
    constexpr size_t SA = (MODE == 0) ? (size_t)QDIM * EDIM : (size_t)QDIM * KDIM;
    constexpr size_t SB = (MODE == 0) ? (size_t)KDIM * EDIM : (size_t)EDIM * KDIM;
    constexpr size_t SC = (MODE == 0) ? (size_t)QDIM * KDIM : (size_t)QDIM * EDIM;
    constexpr int NITER  = KTOT / KCH;            // 16 / 32
    constexpr int NSTAGE = (MODE == 0) ? 3 : 2;
    constexpr int DEPTH  = NSTAGE - 1;

    constexpr uint32_t OFF_A  = 0;
    constexpr uint32_t OFF_B  = TILE16K;
    constexpr uint32_t OFF_BL = 2 * TILE16K;      // MODE 1 only
    constexpr uint32_t STAGE  = (MODE == 0) ? 2 * TILE16K : 3 * TILE16K;

    extern __shared__ __align__(256) uint8_t smem[];
    const uint32_t sb = smem_u32(smem);

    const int tid  = threadIdx.x;
    const int lane = tid & 31;
    const int wid  = tid >> 5;
    const int wm   = (wid >> 2) * 64;
    const int wn   = (wid & 3) * 32;
    const int b    = blockIdx.z;
    const int m0   = blockIdx.y * 128;
    const int n0   = blockIdx.x * 128;

    const fp16* Ah = ((MODE == 0) ? g_Qh : g_Ph)  + b * SA + (size_t)m0 * LDA;
    const fp16* Al = g_Ql + b * SA + (size_t)m0 * LDA;
    const fp16* Bh = ((MODE == 0) ? g_Kh : g_Vth) + b * SB + (size_t)n0 * LDB;
    const fp16* Bl = ((MODE == 0) ? g_Kl : g_Vtl) + b * SB + (size_t)n0 * LDB;
    float* C = ((MODE == 0) ? g_E : Oout) + b * SC;

    float acc[4][4][4];
    #pragma unroll
    for (int i = 0; i < 4; i++)
        #pragma unroll
        for (int j = 0; j < 4; j++)
            #pragma unroll
            for (int q = 0; q < 4; q++) acc[i][j][q] = 0.0f;

    const int a_r15 = lane & 15;
    const int c_hi  = lane >> 4;

    // Full fill of one stage (prologue only)
    auto fill_full = [&](int stage, int ck) {
        const uint32_t st = sb + (uint32_t)stage * STAGE;
        const int k0 = ck * KCH;
        if (MODE == 0) {
            cp_pack(st + OFF_A, Ah + k0, Al + k0, LDA, tid);
            cp_pack(st + OFF_B, Bh + k0, Bl + k0, LDB, tid);
        } else {
            cp_tile(st + OFF_A,  Ah + k0, LDA, tid);
            cp_tile(st + OFF_B,  Bh + k0, LDB, tid);
            cp_tile(st + OFF_BL, Bl + k0, LDB, tid);
        }
        CP_COMMIT();
    };

    #pragma unroll
    for (int d = 0; d < DEPTH; ++d) fill_full(d, d);

    for (int it = 0; it < NITER; ++it) {
        if (it + DEPTH <= NITER) {
            if (DEPTH == 2 && it + 2 <= NITER && it + 1 < NITER) CP_WAIT1();
            else CP_WAIT0();
        }
        __syncthreads();                         // chunk it visible; target
                                                 // stage drained by all warps
        const uint32_t SBASE = sb + (uint32_t)(it % NSTAGE) * STAGE;
        const bool doFill = (it + DEPTH < NITER);
        const uint32_t FST = sb + (uint32_t)((it + DEPTH) % NSTAGE) * STAGE;
        const int k0f = (it + DEPTH) * KCH;

        // One fill part = one cp.async per thread.
        auto fillp = [&](int p) {
            if (MODE == 0) {
                int idx = tid + (p & 3) * 256;
                int r = idx >> 3, c = idx & 7;
                const fp16* sH = (p < 4) ? Ah : Bh;
                const fp16* sL = (p < 4) ? Al : Bl;
                const size_t rb = (size_t)((p < 4) ? LDA : LDB) * 2;
                const char* s = (c < 4)
                    ? (const char*)(sH + k0f) + (size_t)r * rb + c * 16
                    : (const char*)(sL + k0f) + (size_t)r * rb + (c - 4) * 16;
                uint32_t dst = FST + ((p < 4) ? OFF_A : OFF_B)
                    + (uint32_t)r * 128u + (uint32_t)((c ^ (r & 7)) << 4);
                CP_ASYNC16(dst, s);
            } else {
                int t = p >> 2, sub = p & 3;
                int rr = sub * 32 + (tid >> 3);
                int cc = tid & 7;
                const fp16* s0 = (t == 0) ? Ah : (t == 1) ? Bh : Bl;
                const size_t rb = (size_t)((t == 0) ? LDA : LDB) * 2;
                const char* s = (const char*)(s0 + k0f) + (size_t)rr * rb + cc * 16;
                uint32_t dst = FST + (uint32_t)t * TILE16K
                    + (uint32_t)rr * 128u + (uint32_t)((cc ^ (rr & 7)) << 4);
                CP_ASYNC16(dst, s);
            }
        };

        if (MODE == 0) {
            // 6 MMA steps; 8 fill parts drip: {2,1,1,2,1,1}
            uint32_t af[4][4], bfh[2][4], bfl[2][4];
            // kk = 0
            lds_a(SBASE + OFF_A, 0, wm, a_r15, c_hi, af);
            lds_b(SBASE + OFF_B, 0, wn, a_r15, c_hi, bfh);
            lds_b(SBASE + OFF_B, 4, wn, a_r15, c_hi, bfl);
            mma_step(acc, af, bfh);
            if (doFill) { fillp(0); fillp(1); }
            mma_step(acc, af, bfl);
            if (doFill) { fillp(2); }
            lds_a(SBASE + OFF_A, 4, wm, a_r15, c_hi, af);
            mma_step(acc, af, bfh);
            if (doFill) { fillp(3); }
            // kk = 1
            lds_a(SBASE + OFF_A, 2, wm, a_r15, c_hi, af);
            lds_b(SBASE + OFF_B, 2, wn, a_r15, c_hi, bfh);
            lds_b(SBASE + OFF_B, 6, wn, a_r15, c_hi, bfl);
            mma_step(acc, af, bfh);
            if (doFill) { fillp(4); fillp(5); }
            mma_step(acc, af, bfl);
            if (doFill) { fillp(6); }
            lds_a(SBASE + OFF_A, 6, wm, a_r15, c_hi, af);
            mma_step(acc, af, bfh);
            if (doFill) { fillp(7); CP_COMMIT(); }
        } else {
            // 8 MMA steps; 12 fill parts front-loaded {3,3,3,3,0,0,0,0}
            #pragma unroll
            for (int kk = 0; kk < 4; ++kk) {
                uint32_t af[4][4], bfh[2][4], bfl[2][4];
                lds_a(SBASE + OFF_A,  kk * 2, wm, a_r15, c_hi, af);
                lds_b(SBASE + OFF_B,  kk * 2, wn, a_r15, c_hi, bfh);
                lds_b(SBASE + OFF_BL, kk * 2, wn, a_r15, c_hi, bfl);
                mma_step(acc, af, bfh);
                if (kk < 2 && doFill) {
                    fillp(kk * 6 + 0); fillp(kk * 6 + 1); fillp(kk * 6 + 2);
                }
                mma_step(acc, af, bfl);
                if (kk < 2 && doFill) {
                    fillp(kk * 6 + 3); fillp(kk * 6 + 4); fillp(kk * 6 + 5);
                    if (kk == 1) CP_COMMIT();
                }
            }
        }
    }
    CP_WAIT0();

    // Epilogue
    const int g  = lane >> 2;
    const int ti = lane & 3;
    #pragma unroll
    for (int mi = 0; mi < 4; ++mi) {
        #pragma unroll
        for (int ni = 0; ni < 4; ++ni) {
            const int row = m0 + wm + mi * 16 + g;
            const int col = n0 + wn + ni * 8 + ti * 2;
            *(float2*)&C[(size_t)row * LDC + col] =
                make_float2(acc[mi][ni][0], acc[mi][ni][1]);
            *(float2*)&C[(size_t)(row + 8) * LDC + col] =
                make_float2(acc[mi][ni][2], acc[mi][ni][3]);
        }
    }
}

// ---------------------------------------------------------------------------
extern "C" void kernel_launch(void* const* d_in, const int* in_sizes, int n_in,
                              void* d_out, int out_size)
{
    const float* Q = (const float*)d_in[0];
    const float* K = (const float*)d_in[1];
    const float* V = (const float*)d_in[2];
    float*       O = (float*)d_out;

    static cudaStream_t s_side = nullptr;
    static cudaEvent_t  s_fork = nullptr, s_join = nullptr;
    if (s_side == nullptr) {
        cudaStreamCreateWithFlags(&s_side, cudaStreamNonBlocking);
        cudaEventCreateWithFlags(&s_fork, cudaEventDisableTiming);
        cudaEventCreateWithFlags(&s_join, cudaEventDisableTiming);
    }

    cudaFuncSetAttribute(hgemm3_kernel<0>, cudaFuncAttributeMaxDynamicSharedMemorySize, 98304);
    cudaFuncSetAttribute(hgemm3_kernel<1>, cudaFuncAttributeMaxDynamicSharedMemorySize, 98304);

    // Side stream: V-prep overlaps QK GEMM (compute-bound).
    cudaEventRecord(s_fork, 0);
    cudaStreamWaitEvent(s_side, s_fork, 0);
    vtrans_kernel<<<dim3(KDIM / 32, EDIM / 32, NB), 256, 0, s_side>>>(V);
    cudaEventRecord(s_join, s_side);

    const int n4 = NB * QDIM * EDIM / 4;
    split2_kernel<<<dim3((n4 + 255) / 256, 2), 256>>>(Q, K, n4);

    hgemm3_kernel<0><<<dim3(KDIM / 128, QDIM / 128, NB), 256, 98304>>>(nullptr);

    softmax_split_kernel<<<NB * QDIM, 256>>>();

    cudaStreamWaitEvent(0, s_join, 0);
    hgemm3_kernel<1><<<dim3(EDIM / 128, QDIM / 128, NB), 256, 98304>>>(O);
}

// round 13
// speedup vs baseline: 1.1377x; 1.1377x over previous
#include <cuda_runtime.h>
#include <cuda_fp16.h>
#include <cstdint>

#define NB   8
#define QDIM 2048
#define KDIM 2048
#define EDIM 512

typedef __half fp16;

// ---------------------------------------------------------------------------
// Device-global scratch (allocation-guard-safe)
// ---------------------------------------------------------------------------
__device__ __align__(256) fp16  g_Qh[(size_t)NB * QDIM * EDIM];
__device__ __align__(256) fp16  g_Ql[(size_t)NB * QDIM * EDIM];
__device__ __align__(256) fp16  g_Kh[(size_t)NB * KDIM * EDIM];
__device__ __align__(256) fp16  g_Kl[(size_t)NB * KDIM * EDIM];
__device__ __align__(256) fp16  g_Vth[(size_t)NB * EDIM * KDIM];  // V^T [b][e][k]
__device__ __align__(256) fp16  g_Vtl[(size_t)NB * EDIM * KDIM];
__device__ __align__(256) float g_E  [(size_t)NB * QDIM * KDIM];  // logits
__device__ __align__(256) fp16  g_Ph [(size_t)NB * QDIM * KDIM];  // softmax (hi only)

// ---------------------------------------------------------------------------
// PTX helpers (plain sm_80/90 features only — virtual arch is compute_103)
// ---------------------------------------------------------------------------
__device__ __forceinline__ uint32_t smem_u32(const void* p) {
    uint32_t a;
    asm("{ .reg .u64 t; cvta.to.shared.u64 t, %1; cvt.u32.u64 %0, t; }" : "=r"(a) : "l"(p));
    return a;
}

__device__ __forceinline__ uint32_t h2_u32(__half2 h) {
    union { __half2 h; uint32_t u; } c;
    c.h = h;
    return c.u;
}

#define CP_ASYNC16(dst, src) \
    asm volatile("cp.async.cg.shared.global [%0], [%1], 16;" :: "r"(dst), "l"(src))

// mbarrier ops
#define MBAR_INIT(mb, c)  asm volatile("mbarrier.init.shared.b64 [%0], %1;" :: "r"(mb), "r"(c) : "memory")
#define MBAR_ARRIVE(mb)   asm volatile("mbarrier.arrive.shared.b64 _, [%0];" :: "r"(mb) : "memory")
// arrival fires when this thread's prior cp.asyncs complete (.noinc: counted
// against the init count)
#define CP_MBAR_ARRIVE(mb) \
    asm volatile("cp.async.mbarrier.arrive.noinc.shared.b64 [%0];" :: "r"(mb) : "memory")

#define MBAR_WAIT(mb, par) do {                                             \
    uint32_t _m = (mb), _p = (par), _done;                                  \
    asm volatile("{\n\t.reg .pred p;\n\t"                                   \
        "mbarrier.try_wait.parity.acquire.cta.shared::cta.b64 p, [%1], %2;\n\t" \
        "selp.b32 %0, 1, 0, p;\n\t}" : "=r"(_done) : "r"(_m), "r"(_p) : "memory"); \
    if (!_done) {                                                           \
        asm volatile("{\n\t.reg .pred P1;\n\t"                              \
            "WL_%=:\n\t"                                                    \
            "mbarrier.try_wait.parity.acquire.cta.shared::cta.b64 P1, [%0], %1, 0x989680;\n\t" \
            "@P1 bra.uni WD_%=;\n\t"                                        \
            "bra.uni WL_%=;\n\t"                                            \
            "WD_%=:\n\t}" :: "r"(_m), "r"(_p) : "memory");                  \
    }                                                                        \
} while (0)

#define LDSM_X4(r0, r1, r2, r3, a)                                          \
    asm volatile("ldmatrix.sync.aligned.m8n8.x4.shared.b16 {%0,%1,%2,%3}, [%4];" \
        : "=r"(r0), "=r"(r1), "=r"(r2), "=r"(r3) : "r"(a))

#define MMA16816(d, a, b0, b1)                                              \
    asm volatile("mma.sync.aligned.m16n8k16.row.col.f32.f16.f16.f32 "       \
        "{%0,%1,%2,%3},{%4,%5,%6,%7},{%8,%9},{%0,%1,%2,%3};"                \
        : "+f"((d)[0]), "+f"((d)[1]), "+f"((d)[2]), "+f"((d)[3])            \
        : "r"((a)[0]), "r"((a)[1]), "r"((a)[2]), "r"((a)[3]),               \
          "r"(b0), "r"(b1))

// ---------------------------------------------------------------------------
// Elementwise fp32 -> fp16 hi/lo split, Q and K in one launch (blockIdx.y)
// ---------------------------------------------------------------------------
__global__ __launch_bounds__(256)
void split2_kernel(const float* __restrict__ Q, const float* __restrict__ K,
                   int n4)
{
    const int which = blockIdx.y;
    const float* X = which ? K : Q;
    fp16* Xh = which ? g_Kh : g_Qh;
    fp16* Xl = which ? g_Kl : g_Ql;
    int i = blockIdx.x * 256 + threadIdx.x;
    if (i >= n4) return;
    float4 v = ((const float4*)X)[i];
    fp16 h0 = __float2half_rn(v.x), h1 = __float2half_rn(v.y);
    fp16 h2 = __float2half_rn(v.z), h3 = __float2half_rn(v.w);
    fp16 l0 = __float2half_rn(v.x - __half2float(h0));
    fp16 l1 = __float2half_rn(v.y - __half2float(h1));
    fp16 l2 = __float2half_rn(v.z - __half2float(h2));
    fp16 l3 = __float2half_rn(v.w - __half2float(h3));
    ((__half2*)Xh)[2 * i]     = __half2(h0, h1);
    ((__half2*)Xh)[2 * i + 1] = __half2(h2, h3);
    ((__half2*)Xl)[2 * i]     = __half2(l0, l1);
    ((__half2*)Xl)[2 * i + 1] = __half2(l2, l3);
}

// ---------------------------------------------------------------------------
// V [b][k][e] fp32 -> V^T [b][e][k] fp16 hi/lo
// ---------------------------------------------------------------------------
__global__ __launch_bounds__(256)
void vtrans_kernel(const float* __restrict__ V)
{
    __shared__ float t[32][33];
    const int b  = blockIdx.z;
    const int k0 = blockIdx.x * 32;
    const int e0 = blockIdx.y * 32;
    const int tx = threadIdx.x & 31;
    const int ty = threadIdx.x >> 5;
    const float* Vb = V + (size_t)b * KDIM * EDIM;

    #pragma unroll
    for (int j = 0; j < 4; j++)
        t[ty + j * 8][tx] = Vb[(size_t)(k0 + ty + j * 8) * EDIM + e0 + tx];
    __syncthreads();

    #pragma unroll
    for (int j = 0; j < 4; j++) {
        int e = e0 + ty + j * 8;
        int k = k0 + tx;
        float x = t[tx][ty + j * 8];
        fp16 h = __float2half_rn(x);
        fp16 l = __float2half_rn(x - __half2float(h));
        size_t o = (size_t)b * EDIM * KDIM + (size_t)e * KDIM + k;
        g_Vth[o] = h;
        g_Vtl[o] = l;
    }
}

// ---------------------------------------------------------------------------
// Row softmax of g_E -> fp16 (hi only) in g_Ph  (float4 I/O)
// ---------------------------------------------------------------------------
__global__ __launch_bounds__(256)
void softmax_split_kernel()
{
    const size_t row = blockIdx.x;
    const float* p = g_E + row * (size_t)KDIM;
    const int tid = threadIdx.x;

    float4 va = ((const float4*)p)[tid];
    float4 vb = ((const float4*)p)[tid + 256];

    float m = fmaxf(fmaxf(fmaxf(va.x, va.y), fmaxf(va.z, va.w)),
                    fmaxf(fmaxf(vb.x, vb.y), fmaxf(vb.z, vb.w)));

    __shared__ float red[8];
    #pragma unroll
    for (int off = 16; off > 0; off >>= 1) m = fmaxf(m, __shfl_xor_sync(~0u, m, off));
    if ((tid & 31) == 0) red[tid >> 5] = m;
    __syncthreads();
    if (tid < 8) {
        float t = red[tid];
        #pragma unroll
        for (int off = 4; off > 0; off >>= 1) t = fmaxf(t, __shfl_xor_sync(0xFFu, t, off));
        red[tid] = t;
    }
    __syncthreads();
    m = red[0];

    va.x = __expf(va.x - m); va.y = __expf(va.y - m);
    va.z = __expf(va.z - m); va.w = __expf(va.w - m);
    vb.x = __expf(vb.x - m); vb.y = __expf(vb.y - m);
    vb.z = __expf(vb.z - m); vb.w = __expf(vb.w - m);
    float s = (va.x + va.y) + (va.z + va.w) + (vb.x + vb.y) + (vb.z + vb.w);

    __shared__ float red2[8];
    #pragma unroll
    for (int off = 16; off > 0; off >>= 1) s += __shfl_xor_sync(~0u, s, off);
    if ((tid & 31) == 0) red2[tid >> 5] = s;
    __syncthreads();
    if (tid < 8) {
        float t = red2[tid];
        #pragma unroll
        for (int off = 4; off > 0; off >>= 1) t += __shfl_xor_sync(0xFFu, t, off);
        red2[tid] = t;
    }
    __syncthreads();
    const float inv = 1.0f / red2[0];

    fp16* ph = g_Ph + row * (size_t)KDIM;
    __half2 hh[4];
    hh[0] = __half2(__float2half_rn(va.x * inv), __float2half_rn(va.y * inv));
    hh[1] = __half2(__float2half_rn(va.z * inv), __float2half_rn(va.w * inv));
    hh[2] = __half2(__float2half_rn(vb.x * inv), __float2half_rn(vb.y * inv));
    hh[3] = __half2(__float2half_rn(vb.z * inv), __float2half_rn(vb.w * inv));
    *(uint2*)&ph[tid * 4]        = make_uint2(h2_u32(hh[0]), h2_u32(hh[1]));
    *(uint2*)&ph[1024 + tid * 4] = make_uint2(h2_u32(hh[2]), h2_u32(hh[3]));
}

// ---------------------------------------------------------------------------
// HMMA split-fp16 GEMM: 2 CTAs/SM + mbarrier producer/consumer pipeline.
// NO __syncthreads in the mainloop — warps rendezvous on data (full/empty
// mbarriers per stage), so fast warps slide ahead and cover slow warps.
//   MODE 0 (3 passes): E = Q.K^T. K-chunk 32, packed 128B rows [hi32|lo32],
//                      3 stages x 32KB, fill-after-consume (2-chunk slack).
//   MODE 1 (2 passes): O = P.V.  K-chunk 64, tiles Ph/Vh/Vl, 2 stages x 48KB,
//                      fill-before-consume (1-chunk slack).
// CTA tile 128x128, 256 threads (8 warps 2x4), warp tile 64x32.
// ---------------------------------------------------------------------------
#define TILE16K 16384u

__device__ __forceinline__ void cp_pack(uint32_t dstbase, const fp16* srcH,
                                        const fp16* srcL, int ld, int tid)
{
    const char* sh = (const char*)srcH;
    const char* sl = (const char*)srcL;
    const size_t row_bytes = (size_t)ld * 2;
    #pragma unroll
    for (int p = 0; p < 4; ++p) {
        int idx = tid + p * 256;
        int r = idx >> 3;
        int c = idx & 7;
        const char* src = (c < 4) ? sh + (size_t)r * row_bytes + c * 16
                                  : sl + (size_t)r * row_bytes + (c - 4) * 16;
        uint32_t dst = dstbase + (uint32_t)r * 128u + (uint32_t)((c ^ (r & 7)) << 4);
        CP_ASYNC16(dst, src);
    }
}

__device__ __forceinline__ void cp_tile(uint32_t dstbase, const fp16* src,
                                        int ld, int tid)
{
    const char* s = (const char*)src;
    const size_t row_bytes = (size_t)ld * 2;
    const int c = tid & 7;
    #pragma unroll
    for (int r0 = 0; r0 < 128; r0 += 32) {
        int r = r0 + (tid >> 3);
        uint32_t dst = dstbase + (uint32_t)r * 128u + (uint32_t)((c ^ (r & 7)) << 4);
        CP_ASYNC16(dst, s + (size_t)r * row_bytes + c * 16);
    }
}

__device__ __forceinline__ void lds_a(uint32_t base, int cbase, int wm,
                                      int a_r15, int c_hi, uint32_t af[4][4])
{
    #pragma unroll
    for (int mi = 0; mi < 4; ++mi) {
        const int row = wm + mi * 16 + a_r15;
        const uint32_t addr = base + (uint32_t)row * 128u
            + (uint32_t)(((cbase + c_hi) ^ (row & 7)) << 4);
        LDSM_X4(af[mi][0], af[mi][1], af[mi][2], af[mi][3], addr);
    }
}

__device__ __forceinline__ void lds_b(uint32_t base, int cbase, int wn,
                                      int a_r15, int c_hi, uint32_t bf[2][4])
{
    #pragma unroll
    for (int nj = 0; nj < 2; ++nj) {
        const int row = wn + nj * 16 + a_r15;
        const uint32_t addr = base + (uint32_t)row * 128u
            + (uint32_t)(((cbase + c_hi) ^ (row & 7)) << 4);
        LDSM_X4(bf[nj][0], bf[nj][1], bf[nj][2], bf[nj][3], addr);
    }
}

__device__ __forceinline__ void mma_step(float acc[4][4][4],
                                         uint32_t af[4][4], uint32_t bf[2][4])
{
    #pragma unroll
    for (int mi = 0; mi < 4; ++mi) {
        #pragma unroll
        for (int ni = 0; ni < 4; ++ni) {
            const uint32_t b0 = bf[ni >> 1][(ni & 1) ? 1 : 0];
            const uint32_t b1 = bf[ni >> 1][(ni & 1) ? 3 : 2];
            MMA16816(acc[mi][ni], af[mi], b0, b1);
        }
    }
}

template <int MODE>
__global__ __launch_bounds__(256, 2)
void hgemm3_kernel(float* __restrict__ Oout)
{
    constexpr int LDA  = (MODE == 0) ? EDIM : KDIM;
    constexpr int LDB  = (MODE == 0) ? EDIM : KDIM;
    constexpr int LDC  = (MODE == 0) ? KDIM : EDIM;
    constexpr int KTOT = (MODE == 0) ? EDIM : KDIM;
    constexpr int KCH  = (MODE == 0) ? 32 : 64;
    constexpr size_t SA = (MODE == 0) ? (size_t)QDIM * EDIM : (size_t)QDIM * KDIM;
    constexpr size_t SB = (MODE == 0) ? (size_t)KDIM * EDIM : (size_t)EDIM * KDIM;
    constexpr size_t SC = (MODE == 0) ? (size_t)QDIM * KDIM : (size_t)QDIM * EDIM;
    constexpr int NITER  = KTOT / KCH;            // 16 / 32
    constexpr int NSTAGE = (MODE == 0) ? 3 : 2;
    constexpr int DEPTH  = NSTAGE - 1;

    constexpr uint32_t OFF_A  = 0;
    constexpr uint32_t OFF_B  = TILE16K;
    constexpr uint32_t OFF_BL = 2 * TILE16K;      // MODE 1 only
    constexpr uint32_t STAGE  = (MODE == 0) ? 2 * TILE16K : 3 * TILE16K;
    constexpr uint32_t TILES0 = 256;              // tiles start (after mbarriers)

    extern __shared__ __align__(256) uint8_t smem[];
    const uint32_t sb   = smem_u32(smem);
    const uint32_t tb   = sb + TILES0;
    // mbarriers: full[0..2] at sb+0,8,16 ; empty[0..2] at sb+24,32,40
    const uint32_t mbF0 = sb;
    const uint32_t mbE0 = sb + 24;

    const int tid  = threadIdx.x;
    const int lane = tid & 31;
    const int wid  = tid >> 5;
    const int wm   = (wid >> 2) * 64;
    const int wn   = (wid & 3) * 32;
    const int b    = blockIdx.z;
    const int m0   = blockIdx.y * 128;
    const int n0   = blockIdx.x * 128;

    const fp16* Ah = ((MODE == 0) ? g_Qh : g_Ph)  + b * SA + (size_t)m0 * LDA;
    const fp16* Al = g_Ql + b * SA + (size_t)m0 * LDA;
    const fp16* Bh = ((MODE == 0) ? g_Kh : g_Vth) + b * SB + (size_t)n0 * LDB;
    const fp16* Bl = ((MODE == 0) ? g_Kl : g_Vtl) + b * SB + (size_t)n0 * LDB;
    float* C = ((MODE == 0) ? g_E : Oout) + b * SC;

    float acc[4][4][4];
    #pragma unroll
    for (int i = 0; i < 4; i++)
        #pragma unroll
        for (int j = 0; j < 4; j++)
            #pragma unroll
            for (int q = 0; q < 4; q++) acc[i][j][q] = 0.0f;

    const int a_r15 = lane & 15;
    const int c_hi  = lane >> 4;

    // Init mbarriers (one thread), then one CTA barrier so all see them.
    if (tid == 0) {
        #pragma unroll
        for (int s = 0; s < NSTAGE; ++s) {
            MBAR_INIT(mbF0 + s * 8u, 256);
            MBAR_INIT(mbE0 + s * 8u, 256);
        }
    }
    __syncthreads();

    // Fill stage s with chunk ck; every thread issues its copies then a
    // completion-arrive on full[s].
    auto fill = [&](int s, int ck) {
        const uint32_t st = tb + (uint32_t)s * STAGE;
        const int k0 = ck * KCH;
        if (MODE == 0) {
            cp_pack(st + OFF_A, Ah + k0, Al + k0, LDA, tid);
            cp_pack(st + OFF_B, Bh + k0, Bl + k0, LDB, tid);
        } else {
            cp_tile(st + OFF_A,  Ah + k0, LDA, tid);
            cp_tile(st + OFF_B,  Bh + k0, LDB, tid);
            cp_tile(st + OFF_BL, Bl + k0, LDB, tid);
        }
        CP_MBAR_ARRIVE(mbF0 + s * 8u);
    };

    // Prologue: fill DEPTH stages (chunks 0..DEPTH-1)
    #pragma unroll
    for (int d = 0; d < DEPTH; ++d) fill(d, d);

    for (int it = 0; it < NITER; ++it) {
        const int s   = it % NSTAGE;
        const int phF = (it / NSTAGE) & 1;

        if (MODE == 1) {
            // fill-before-consume (1-chunk slack)
            const int ck = it + 1;
            if (ck < NITER) {
                const int s2 = ck % NSTAGE;
                if (ck >= NSTAGE) {
                    const int phE = ((ck / NSTAGE) - 1) & 1;
                    MBAR_WAIT(mbE0 + s2 * 8u, phE);
                }
                fill(s2, ck);
            }
        }

        MBAR_WAIT(mbF0 + s * 8u, phF);           // chunk it ready
        const uint32_t SBASE = tb + (uint32_t)s * STAGE;

        if (MODE == 0) {
            #pragma unroll
            for (int kk = 0; kk < 2; ++kk) {
                uint32_t af[4][4], bfh[2][4], bfl[2][4];
                lds_a(SBASE + OFF_A, kk * 2,     wm, a_r15, c_hi, af);
                lds_b(SBASE + OFF_B, kk * 2,     wn, a_r15, c_hi, bfh);
                lds_b(SBASE + OFF_B, 4 + kk * 2, wn, a_r15, c_hi, bfl);
                mma_step(acc, af, bfh);
                mma_step(acc, af, bfl);
                lds_a(SBASE + OFF_A, 4 + kk * 2, wm, a_r15, c_hi, af);
                mma_step(acc, af, bfh);
            }
        } else {
            #pragma unroll
            for (int kk = 0; kk < 4; ++kk) {
                uint32_t af[4][4], bfh[2][4], bfl[2][4];
                lds_a(SBASE + OFF_A,  kk * 2, wm, a_r15, c_hi, af);
                lds_b(SBASE + OFF_B,  kk * 2, wn, a_r15, c_hi, bfh);
                lds_b(SBASE + OFF_BL, kk * 2, wn, a_r15, c_hi, bfl);
                mma_step(acc, af, bfh);
                mma_step(acc, af, bfl);
            }
        }

        MBAR_ARRIVE(mbE0 + s * 8u);              // stage drained by this thread

        if (MODE == 0) {
            // fill-after-consume (2-chunk slack)
            const int ck = it + DEPTH;
            if (ck < NITER) {
                const int s2 = ck % NSTAGE;
                if (ck >= NSTAGE) {
                    const int phE = ((ck / NSTAGE) - 1) & 1;
                    MBAR_WAIT(mbE0 + s2 * 8u, phE);
                }
                fill(s2, ck);
            }
        }
    }

    // Epilogue
    const int g  = lane >> 2;
    const int ti = lane & 3;
    #pragma unroll
    for (int mi = 0; mi < 4; ++mi) {
        #pragma unroll
        for (int ni = 0; ni < 4; ++ni) {
            const int row = m0 + wm + mi * 16 + g;
            const int col = n0 + wn + ni * 8 + ti * 2;
            *(float2*)&C[(size_t)row * LDC + col] =
                make_float2(acc[mi][ni][0], acc[mi][ni][1]);
            *(float2*)&C[(size_t)(row + 8) * LDC + col] =
                make_float2(acc[mi][ni][2], acc[mi][ni][3]);
        }
    }
}

// ---------------------------------------------------------------------------
extern "C" void kernel_launch(void* const* d_in, const int* in_sizes, int n_in,
                              void* d_out, int out_size)
{
    const float* Q = (const float*)d_in[0];
    const float* K = (const float*)d_in[1];
    const float* V = (const float*)d_in[2];
    float*       O = (float*)d_out;

    static cudaStream_t s_side = nullptr;
    static cudaEvent_t  s_fork = nullptr, s_join = nullptr;
    if (s_side == nullptr) {
        cudaStreamCreateWithFlags(&s_side, cudaStreamNonBlocking);
        cudaEventCreateWithFlags(&s_fork, cudaEventDisableTiming);
        cudaEventCreateWithFlags(&s_join, cudaEventDisableTiming);
    }

    const int SMEM = 256 + 98304;   // mbarriers + 96KB tiles
    cudaFuncSetAttribute(hgemm3_kernel<0>, cudaFuncAttributeMaxDynamicSharedMemorySize, SMEM);
    cudaFuncSetAttribute(hgemm3_kernel<1>, cudaFuncAttributeMaxDynamicSharedMemorySize, SMEM);

    // Side stream: V-prep overlaps QK GEMM (compute-bound).
    cudaEventRecord(s_fork, 0);
    cudaStreamWaitEvent(s_side, s_fork, 0);
    vtrans_kernel<<<dim3(KDIM / 32, EDIM / 32, NB), 256, 0, s_side>>>(V);
    cudaEventRecord(s_join, s_side);

    const int n4 = NB * QDIM * EDIM / 4;
    split2_kernel<<<dim3((n4 + 255) / 256, 2), 256>>>(Q, K, n4);

    hgemm3_kernel<0><<<dim3(KDIM / 128, QDIM / 128, NB), 256, SMEM>>>(nullptr);

    softmax_split_kernel<<<NB * QDIM, 256>>>();

    cudaStreamWaitEvent(0, s_join, 0);
    hgemm3_kernel<1><<<dim3(EDIM / 128, QDIM / 128, NB), 256, SMEM>>>(O);
}

// round 14
// speedup vs baseline: 1.3433x; 1.1807x over previous
#include <cuda_runtime.h>
#include <cuda_fp16.h>
#include <cstdint>

#define NB   8
#define QDIM 2048
#define KDIM 2048
#define EDIM 512

typedef __half fp16;

// ---------------------------------------------------------------------------
// Device-global scratch (allocation-guard-safe)
// ---------------------------------------------------------------------------
__device__ __align__(256) fp16  g_Qh[(size_t)NB * QDIM * EDIM];
__device__ __align__(256) fp16  g_Ql[(size_t)NB * QDIM * EDIM];
__device__ __align__(256) fp16  g_Kh[(size_t)NB * KDIM * EDIM];
__device__ __align__(256) fp16  g_Kl[(size_t)NB * KDIM * EDIM];
__device__ __align__(256) fp16  g_Vth[(size_t)NB * EDIM * KDIM];  // V^T hi only
__device__ __align__(256) float g_E  [(size_t)NB * QDIM * KDIM];  // logits
__device__ __align__(256) fp16  g_Ph [(size_t)NB * QDIM * KDIM];  // softmax (hi only)

// ---------------------------------------------------------------------------
// PTX helpers (plain sm_80/90 features only — virtual arch is compute_103)
// ---------------------------------------------------------------------------
__device__ __forceinline__ uint32_t smem_u32(const void* p) {
    uint32_t a;
    asm("{ .reg .u64 t; cvta.to.shared.u64 t, %1; cvt.u32.u64 %0, t; }" : "=r"(a) : "l"(p));
    return a;
}

__device__ __forceinline__ uint32_t h2_u32(__half2 h) {
    union { __half2 h; uint32_t u; } c;
    c.h = h;
    return c.u;
}

#define CP_ASYNC16(dst, src) \
    asm volatile("cp.async.cg.shared.global [%0], [%1], 16;" :: "r"(dst), "l"(src))

#define MBAR_INIT(mb, c)  asm volatile("mbarrier.init.shared.b64 [%0], %1;" :: "r"(mb), "r"(c) : "memory")
#define MBAR_ARRIVE(mb)   asm volatile("mbarrier.arrive.shared.b64 _, [%0];" :: "r"(mb) : "memory")
#define CP_MBAR_ARRIVE(mb) \
    asm volatile("cp.async.mbarrier.arrive.noinc.shared.b64 [%0];" :: "r"(mb) : "memory")

#define MBAR_WAIT(mb, par) do {                                             \
    uint32_t _m = (mb), _p = (par), _done;                                  \
    asm volatile("{\n\t.reg .pred p;\n\t"                                   \
        "mbarrier.try_wait.parity.acquire.cta.shared::cta.b64 p, [%1], %2;\n\t" \
        "selp.b32 %0, 1, 0, p;\n\t}" : "=r"(_done) : "r"(_m), "r"(_p) : "memory"); \
    if (!_done) {                                                           \
        asm volatile("{\n\t.reg .pred P1;\n\t"                              \
            "WL_%=:\n\t"                                                    \
            "mbarrier.try_wait.parity.acquire.cta.shared::cta.b64 P1, [%0], %1, 0x989680;\n\t" \
            "@P1 bra.uni WD_%=;\n\t"                                        \
            "bra.uni WL_%=;\n\t"                                            \
            "WD_%=:\n\t}" :: "r"(_m), "r"(_p) : "memory");                  \
    }                                                                        \
} while (0)

#define LDSM_X4(r0, r1, r2, r3, a)                                          \
    asm volatile("ldmatrix.sync.aligned.m8n8.x4.shared.b16 {%0,%1,%2,%3}, [%4];" \
        : "=r"(r0), "=r"(r1), "=r"(r2), "=r"(r3) : "r"(a))

#define MMA16816(d, a, b0, b1)                                              \
    asm volatile("mma.sync.aligned.m16n8k16.row.col.f32.f16.f16.f32 "       \
        "{%0,%1,%2,%3},{%4,%5,%6,%7},{%8,%9},{%0,%1,%2,%3};"                \
        : "+f"((d)[0]), "+f"((d)[1]), "+f"((d)[2]), "+f"((d)[3])            \
        : "r"((a)[0]), "r"((a)[1]), "r"((a)[2]), "r"((a)[3]),               \
          "r"(b0), "r"(b1))

// ---------------------------------------------------------------------------
// Elementwise fp32 -> fp16 hi/lo split, Q and K in one launch (blockIdx.y)
// ---------------------------------------------------------------------------
__global__ __launch_bounds__(256)
void split2_kernel(const float* __restrict__ Q, const float* __restrict__ K,
                   int n4)
{
    const int which = blockIdx.y;
    const float* X = which ? K : Q;
    fp16* Xh = which ? g_Kh : g_Qh;
    fp16* Xl = which ? g_Kl : g_Ql;
    int i = blockIdx.x * 256 + threadIdx.x;
    if (i >= n4) return;
    float4 v = ((const float4*)X)[i];
    fp16 h0 = __float2half_rn(v.x), h1 = __float2half_rn(v.y);
    fp16 h2 = __float2half_rn(v.z), h3 = __float2half_rn(v.w);
    fp16 l0 = __float2half_rn(v.x - __half2float(h0));
    fp16 l1 = __float2half_rn(v.y - __half2float(h1));
    fp16 l2 = __float2half_rn(v.z - __half2float(h2));
    fp16 l3 = __float2half_rn(v.w - __half2float(h3));
    ((__half2*)Xh)[2 * i]     = __half2(h0, h1);
    ((__half2*)Xh)[2 * i + 1] = __half2(h2, h3);
    ((__half2*)Xl)[2 * i]     = __half2(l0, l1);
    ((__half2*)Xl)[2 * i + 1] = __half2(l2, l3);
}

// ---------------------------------------------------------------------------
// V [b][k][e] fp32 -> V^T [b][e][k] fp16 (hi only)
// ---------------------------------------------------------------------------
__global__ __launch_bounds__(256)
void vtrans_kernel(const float* __restrict__ V)
{
    __shared__ float t[32][33];
    const int b  = blockIdx.z;
    const int k0 = blockIdx.x * 32;
    const int e0 = blockIdx.y * 32;
    const int tx = threadIdx.x & 31;
    const int ty = threadIdx.x >> 5;
    const float* Vb = V + (size_t)b * KDIM * EDIM;

    #pragma unroll
    for (int j = 0; j < 4; j++)
        t[ty + j * 8][tx] = Vb[(size_t)(k0 + ty + j * 8) * EDIM + e0 + tx];
    __syncthreads();

    #pragma unroll
    for (int j = 0; j < 4; j++) {
        int e = e0 + ty + j * 8;
        int k = k0 + tx;
        g_Vth[(size_t)b * EDIM * KDIM + (size_t)e * KDIM + k] =
            __float2half_rn(t[tx][ty + j * 8]);
    }
}

// ---------------------------------------------------------------------------
// Row softmax of g_E -> fp16 (hi only) in g_Ph  (float4 I/O)
// ---------------------------------------------------------------------------
__global__ __launch_bounds__(256)
void softmax_split_kernel()
{
    const size_t row = blockIdx.x;
    const float* p = g_E + row * (size_t)KDIM;
    const int tid = threadIdx.x;

    float4 va = ((const float4*)p)[tid];
    float4 vb = ((const float4*)p)[tid + 256];

    float m = fmaxf(fmaxf(fmaxf(va.x, va.y), fmaxf(va.z, va.w)),
                    fmaxf(fmaxf(vb.x, vb.y), fmaxf(vb.z, vb.w)));

    __shared__ float red[8];
    #pragma unroll
    for (int off = 16; off > 0; off >>= 1) m = fmaxf(m, __shfl_xor_sync(~0u, m, off));
    if ((tid & 31) == 0) red[tid >> 5] = m;
    __syncthreads();
    if (tid < 8) {
        float t = red[tid];
        #pragma unroll
        for (int off = 4; off > 0; off >>= 1) t = fmaxf(t, __shfl_xor_sync(0xFFu, t, off));
        red[tid] = t;
    }
    __syncthreads();
    m = red[0];

    va.x = __expf(va.x - m); va.y = __expf(va.y - m);
    va.z = __expf(va.z - m); va.w = __expf(va.w - m);
    vb.x = __expf(vb.x - m); vb.y = __expf(vb.y - m);
    vb.z = __expf(vb.z - m); vb.w = __expf(vb.w - m);
    float s = (va.x + va.y) + (va.z + va.w) + (vb.x + vb.y) + (vb.z + vb.w);

    __shared__ float red2[8];
    #pragma unroll
    for (int off = 16; off > 0; off >>= 1) s += __shfl_xor_sync(~0u, s, off);
    if ((tid & 31) == 0) red2[tid >> 5] = s;
    __syncthreads();
    if (tid < 8) {
        float t = red2[tid];
        #pragma unroll
        for (int off = 4; off > 0; off >>= 1) t += __shfl_xor_sync(0xFFu, t, off);
        red2[tid] = t;
    }
    __syncthreads();
    const float inv = 1.0f / red2[0];

    fp16* ph = g_Ph + row * (size_t)KDIM;
    __half2 hh[4];
    hh[0] = __half2(__float2half_rn(va.x * inv), __float2half_rn(va.y * inv));
    hh[1] = __half2(__float2half_rn(va.z * inv), __float2half_rn(va.w * inv));
    hh[2] = __half2(__float2half_rn(vb.x * inv), __float2half_rn(vb.y * inv));
    hh[3] = __half2(__float2half_rn(vb.z * inv), __float2half_rn(vb.w * inv));
    *(uint2*)&ph[tid * 4]        = make_uint2(h2_u32(hh[0]), h2_u32(hh[1]));
    *(uint2*)&ph[1024 + tid * 4] = make_uint2(h2_u32(hh[2]), h2_u32(hh[3]));
}

// ---------------------------------------------------------------------------
// HMMA split-fp16 GEMM: 2 CTAs/SM + mbarrier producer/consumer pipeline.
//   MODE 0 (3 passes): E = Q.K^T. K-chunk 32, packed 128B rows [hi32|lo32].
//   MODE 1 (1 pass):   O = Ph.Vh. K-chunk 64, tiles Ph / Vh.
// Both: 3 stages x 32KB = 96KB/CTA, DEPTH 2, fill-after-consume.
// CTA tile 128x128, 256 threads (8 warps 2x4), warp tile 64x32.
// ---------------------------------------------------------------------------
#define TILE16K 16384u

__device__ __forceinline__ void cp_pack(uint32_t dstbase, const fp16* srcH,
                                        const fp16* srcL, int ld, int tid)
{
    const char* sh = (const char*)srcH;
    const char* sl = (const char*)srcL;
    const size_t row_bytes = (size_t)ld * 2;
    #pragma unroll
    for (int p = 0; p < 4; ++p) {
        int idx = tid + p * 256;
        int r = idx >> 3;
        int c = idx & 7;
        const char* src = (c < 4) ? sh + (size_t)r * row_bytes + c * 16
                                  : sl + (size_t)r * row_bytes + (c - 4) * 16;
        uint32_t dst = dstbase + (uint32_t)r * 128u + (uint32_t)((c ^ (r & 7)) << 4);
        CP_ASYNC16(dst, src);
    }
}

__device__ __forceinline__ void cp_tile(uint32_t dstbase, const fp16* src,
                                        int ld, int tid)
{
    const char* s = (const char*)src;
    const size_t row_bytes = (size_t)ld * 2;
    const int c = tid & 7;
    #pragma unroll
    for (int r0 = 0; r0 < 128; r0 += 32) {
        int r = r0 + (tid >> 3);
        uint32_t dst = dstbase + (uint32_t)r * 128u + (uint32_t)((c ^ (r & 7)) << 4);
        CP_ASYNC16(dst, s + (size_t)r * row_bytes + c * 16);
    }
}

__device__ __forceinline__ void lds_a(uint32_t base, int cbase, int wm,
                                      int a_r15, int c_hi, uint32_t af[4][4])
{
    #pragma unroll
    for (int mi = 0; mi < 4; ++mi) {
        const int row = wm + mi * 16 + a_r15;
        const uint32_t addr = base + (uint32_t)row * 128u
            + (uint32_t)(((cbase + c_hi) ^ (row & 7)) << 4);
        LDSM_X4(af[mi][0], af[mi][1], af[mi][2], af[mi][3], addr);
    }
}

__device__ __forceinline__ void lds_b(uint32_t base, int cbase, int wn,
                                      int a_r15, int c_hi, uint32_t bf[2][4])
{
    #pragma unroll
    for (int nj = 0; nj < 2; ++nj) {
        const int row = wn + nj * 16 + a_r15;
        const uint32_t addr = base + (uint32_t)row * 128u
            + (uint32_t)(((cbase + c_hi) ^ (row & 7)) << 4);
        LDSM_X4(bf[nj][0], bf[nj][1], bf[nj][2], bf[nj][3], addr);
    }
}

__device__ __forceinline__ void mma_step(float acc[4][4][4],
                                         uint32_t af[4][4], uint32_t bf[2][4])
{
    #pragma unroll
    for (int mi = 0; mi < 4; ++mi) {
        #pragma unroll
        for (int ni = 0; ni < 4; ++ni) {
            const uint32_t b0 = bf[ni >> 1][(ni & 1) ? 1 : 0];
            const uint32_t b1 = bf[ni >> 1][(ni & 1) ? 3 : 2];
            MMA16816(acc[mi][ni], af[mi], b0, b1);
        }
    }
}

template <int MODE>
__global__ __launch_bounds__(256, 2)
void hgemm3_kernel(float* __restrict__ Oout)
{
    constexpr int LDA  = (MODE == 0) ? EDIM : KDIM;
    constexpr int LDB  = (MODE == 0) ? EDIM : KDIM;
    constexpr int LDC  = (MODE == 0) ? KDIM : EDIM;
    constexpr int KTOT = (MODE == 0) ? EDIM : KDIM;
    constexpr int KCH  = (MODE == 0) ? 32 : 64;
    constexpr size_t SA = (MODE == 0) ? (size_t)QDIM * EDIM : (size_t)QDIM * KDIM;
    constexpr size_t SB = (MODE == 0) ? (size_t)KDIM * EDIM : (size_t)EDIM * KDIM;
    constexpr size_t SC = (MODE == 0) ? (size_t)QDIM * KDIM : (size_t)QDIM * EDIM;
    constexpr int NITER  = KTOT / KCH;            // 16 / 32
    constexpr int NSTAGE = 3;
    constexpr int DEPTH  = 2;

    constexpr uint32_t OFF_A  = 0;
    constexpr uint32_t OFF_B  = TILE16K;
    constexpr uint32_t STAGE  = 2 * TILE16K;      // 32KB both modes
    constexpr uint32_t TILES0 = 256;

    extern __shared__ __align__(256) uint8_t smem[];
    const uint32_t sb   = smem_u32(smem);
    const uint32_t tb   = sb + TILES0;
    const uint32_t mbF0 = sb;
    const uint32_t mbE0 = sb + 24;

    const int tid  = threadIdx.x;
    const int lane = tid & 31;
    const int wid  = tid >> 5;
    const int wm   = (wid >> 2) * 64;
    const int wn   = (wid & 3) * 32;
    const int b    = blockIdx.z;
    const int m0   = blockIdx.y * 128;
    const int n0   = blockIdx.x * 128;

    const fp16* Ah = ((MODE == 0) ? g_Qh : g_Ph)  + b * SA + (size_t)m0 * LDA;
    const fp16* Al = g_Ql + b * SA + (size_t)m0 * LDA;          // MODE 0 only
    const fp16* Bh = ((MODE == 0) ? g_Kh : g_Vth) + b * SB + (size_t)n0 * LDB;
    const fp16* Bl = g_Kl + b * SB + (size_t)n0 * LDB;          // MODE 0 only
    float* C = ((MODE == 0) ? g_E : Oout) + b * SC;

    float acc[4][4][4];
    #pragma unroll
    for (int i = 0; i < 4; i++)
        #pragma unroll
        for (int j = 0; j < 4; j++)
            #pragma unroll
            for (int q = 0; q < 4; q++) acc[i][j][q] = 0.0f;

    const int a_r15 = lane & 15;
    const int c_hi  = lane >> 4;

    if (tid == 0) {
        #pragma unroll
        for (int s = 0; s < NSTAGE; ++s) {
            MBAR_INIT(mbF0 + s * 8u, 256);
            MBAR_INIT(mbE0 + s * 8u, 256);
        }
    }
    __syncthreads();

    auto fill = [&](int s, int ck) {
        const uint32_t st = tb + (uint32_t)s * STAGE;
        const int k0 = ck * KCH;
        if (MODE == 0) {
            cp_pack(st + OFF_A, Ah + k0, Al + k0, LDA, tid);
            cp_pack(st + OFF_B, Bh + k0, Bl + k0, LDB, tid);
        } else {
            cp_tile(st + OFF_A, Ah + k0, LDA, tid);
            cp_tile(st + OFF_B, Bh + k0, LDB, tid);
        }
        CP_MBAR_ARRIVE(mbF0 + s * 8u);
    };

    #pragma unroll
    for (int d = 0; d < DEPTH; ++d) fill(d, d);

    for (int it = 0; it < NITER; ++it) {
        const int s   = it % NSTAGE;
        const int phF = (it / NSTAGE) & 1;

        MBAR_WAIT(mbF0 + s * 8u, phF);
        const uint32_t SBASE = tb + (uint32_t)s * STAGE;

        if (MODE == 0) {
            #pragma unroll
            for (int kk = 0; kk < 2; ++kk) {
                uint32_t af[4][4], bfh[2][4], bfl[2][4];
                lds_a(SBASE + OFF_A, kk * 2,     wm, a_r15, c_hi, af);
                lds_b(SBASE + OFF_B, kk * 2,     wn, a_r15, c_hi, bfh);
                lds_b(SBASE + OFF_B, 4 + kk * 2, wn, a_r15, c_hi, bfl);
                mma_step(acc, af, bfh);
                mma_step(acc, af, bfl);
                lds_a(SBASE + OFF_A, 4 + kk * 2, wm, a_r15, c_hi, af);
                mma_step(acc, af, bfh);
            }
        } else {
            #pragma unroll
            for (int kk = 0; kk < 4; ++kk) {
                uint32_t af[4][4], bfh[2][4];
                lds_a(SBASE + OFF_A, kk * 2, wm, a_r15, c_hi, af);
                lds_b(SBASE + OFF_B, kk * 2, wn, a_r15, c_hi, bfh);
                mma_step(acc, af, bfh);
            }
        }

        MBAR_ARRIVE(mbE0 + s * 8u);

        const int ck = it + DEPTH;
        if (ck < NITER) {
            const int s2 = ck % NSTAGE;
            if (ck >= NSTAGE) {
                const int phE = ((ck / NSTAGE) - 1) & 1;
                MBAR_WAIT(mbE0 + s2 * 8u, phE);
            }
            fill(s2, ck);
        }
    }

    // Epilogue
    const int g  = lane >> 2;
    const int ti = lane & 3;
    #pragma unroll
    for (int mi = 0; mi < 4; ++mi) {
        #pragma unroll
        for (int ni = 0; ni < 4; ++ni) {
            const int row = m0 + wm + mi * 16 + g;
            const int col = n0 + wn + ni * 8 + ti * 2;
            *(float2*)&C[(size_t)row * LDC + col] =
                make_float2(acc[mi][ni][0], acc[mi][ni][1]);
            *(float2*)&C[(size_t)(row + 8) * LDC + col] =
                make_float2(acc[mi][ni][2], acc[mi][ni][3]);
        }
    }
}

// ---------------------------------------------------------------------------
extern "C" void kernel_launch(void* const* d_in, const int* in_sizes, int n_in,
                              void* d_out, int out_size)
{
    const float* Q = (const float*)d_in[0];
    const float* K = (const float*)d_in[1];
    const float* V = (const float*)d_in[2];
    float*       O = (float*)d_out;

    static cudaStream_t s_side = nullptr;
    static cudaEvent_t  s_fork = nullptr, s_join = nullptr;
    if (s_side == nullptr) {
        cudaStreamCreateWithFlags(&s_side, cudaStreamNonBlocking);
        cudaEventCreateWithFlags(&s_fork, cudaEventDisableTiming);
        cudaEventCreateWithFlags(&s_join, cudaEventDisableTiming);
    }

    const int SMEM = 256 + 98304;
    cudaFuncSetAttribute(hgemm3_kernel<0>, cudaFuncAttributeMaxDynamicSharedMemorySize, SMEM);
    cudaFuncSetAttribute(hgemm3_kernel<1>, cudaFuncAttributeMaxDynamicSharedMemorySize, SMEM);

    cudaEventRecord(s_fork, 0);
    cudaStreamWaitEvent(s_side, s_fork, 0);
    vtrans_kernel<<<dim3(KDIM / 32, EDIM / 32, NB), 256, 0, s_side>>>(V);
    cudaEventRecord(s_join, s_side);

    const int n4 = NB * QDIM * EDIM / 4;
    split2_kernel<<<dim3((n4 + 255) / 256, 2), 256>>>(Q, K, n4);

    hgemm3_kernel<0><<<dim3(KDIM / 128, QDIM / 128, NB), 256, SMEM>>>(nullptr);

    softmax_split_kernel<<<NB * QDIM, 256>>>();

    cudaStreamWaitEvent(0, s_join, 0);
    hgemm3_kernel<1><<<dim3(EDIM / 128, QDIM / 128, NB), 256, SMEM>>>(O);
}